// round 13
// baseline (speedup 1.0000x reference)
#include <cuda_runtime.h>
#include <cstdint>
#include <cstddef>

// 3-layer LSTM (H=64), S=2048, B=512, FC(64->2).
// rec: R10 structure (thread owns 4 gate rows of one column, K-quarter each,
//      64 weight regs; tanh.approx; ONE named barrier/step; double-buffered h)
//      + R13: 8-shfl merge only (xor2 batch-swap, then xor1). No folded init,
//      no extra branches.
// proj: R9 version (grid 1024 x 512 thr, 8 rows/iter) - best measured.

#define SQ   2048
#define BB   512
#define HID  64

static __device__ float g_bufA[(size_t)SQ * BB * HID];
static __device__ float g_bufB[(size_t)SQ * BB * HID];
static __device__ float g_xp  [(size_t)SQ * BB * 256];

__device__ __forceinline__ unsigned long long fma2(unsigned long long a,
                                                   unsigned long long b,
                                                   unsigned long long c) {
    unsigned long long d;
    asm("fma.rn.f32x2 %0, %1, %2, %3;" : "=l"(d) : "l"(a), "l"(b), "l"(c));
    return d;
}
__device__ __forceinline__ float lohi(unsigned long long u) {
    union { unsigned long long v; float2 f; } c; c.v = u;
    return c.f.x + c.f.y;
}
__device__ __forceinline__ float tanha(float x) {
    float y; asm("tanh.approx.f32 %0, %1;" : "=f"(y) : "f"(x)); return y;
}
__device__ __forceinline__ float sigf(float x) {
    return fmaf(0.5f, tanha(0.5f * x), 0.5f);
}

// ---------------------------------------------------------------------------
// Recurrence. grid=128 CTAs x 512 threads; grp = tid>>8 owns 2 batches.
// t8 = tid&255: kq = t8&3 (K-quarter), r6 = t8>>2 (column). Thread holds
// Whh rows {r6, 64+r6, 128+r6, 192+r6}, K-quarter kq (64 regs).
// Merge (8 shfl): round A xor2 (batch swap) -> K-half sum for batch fb;
// round B xor1 -> full sum. Local c/h update. ONE bar.sync(grp+1,256)/step.
// MODE: 0 = layer0 (x inline, h->bufA), 1 = mid (xp in, h->bufB),
//       2 = final (xp in, FC->out).
// ---------------------------------------------------------------------------
template <int MODE>
__global__ void __launch_bounds__(512, 1)
lstm_rec(const float* __restrict__ xin,
         const float* __restrict__ Wih, const float* __restrict__ Whh,
         const float* __restrict__ bih, const float* __restrict__ bhh,
         const float* __restrict__ fcw, const float* __restrict__ fcb,
         float* __restrict__ out)
{
    // h[col j] at hq[buf][local batch][j>>4][j&15]; quarter stride 20 floats
    // (80B): 16B-aligned, 4 kq broadcast groups on disjoint banks.
    __shared__ __align__(16) float hq[2][4][4][20];
    __shared__ __align__(16) float4 xsm[2][4];        // MODE 0 only

    const int tid = threadIdx.x;
    const int grp = tid >> 8;
    const int t8  = tid & 255;
    const int kq  = t8 & 3;
    const int r6  = t8 >> 2;
    const int fb  = kq >> 1;                 // batch this lane finalizes
    const int lb  = 2 * grp + fb;            // local batch 0..3
    const int gb  = blockIdx.x * 4 + lb;     // global batch
    const int lb0 = 2 * grp, lb1 = 2 * grp + 1;
    // MODE 0 x-staging: per-group writers (t8 < 8), batch 2grp + (t8>>2)
    const int xlb = 2 * grp + ((t8 >> 2) & 1);
    const int xgb = blockIdx.x * 4 + xlb;

    unsigned long long w[4][8];
#pragma unroll
    for (int g = 0; g < 4; g++)
#pragma unroll
        for (int m2 = 0; m2 < 8; m2++)
            w[g][m2] = *(const unsigned long long*)
                (Whh + (size_t)(64 * g + r6) * HID + 16 * kq + 2 * m2);

    float4 wi[4]; float bias[4];
    if (MODE == 0) {
#pragma unroll
        for (int g = 0; g < 4; g++) {
            wi[g]   = *(const float4*)(Wih + (size_t)(64 * g + r6) * 4);
            bias[g] = bih[64 * g + r6] + bhh[64 * g + r6];
        }
    }

    float c = 0.f;
    if ((kq & 1) == 0) hq[0][lb][r6 >> 4][r6 & 15] = 0.f;

    // xp queues (distance 2), all lanes (own batch fb)
    const size_t xstr = (size_t)BB * 256;
    const float* xb = g_xp + (size_t)gb * 256 + r6;
    float xq[4], xm[4];
    if (MODE != 0) {
#pragma unroll
        for (int g = 0; g < 4; g++) {
            xq[g] = xb[64 * g];
            xm[g] = xb[xstr + 64 * g];
        }
    } else if (t8 < 8) {
        xsm[0][xlb] = *(const float4*)(xin + (size_t)xgb * SQ * 4);
    }
    __syncthreads();

    float* dst = (MODE == 0) ? g_bufA : g_bufB;

    for (int t = 0; t < SQ; t++) {
        const int p = t & 1;

        float xn[4]; float4 xnv;
        if (MODE != 0) {
            if (t + 2 < SQ) {
                const float* q = xb + (size_t)(t + 2) * xstr;
#pragma unroll
                for (int g = 0; g < 4; g++) xn[g] = q[64 * g];
            } else {
#pragma unroll
                for (int g = 0; g < 4; g++) xn[g] = 0.f;
            }
        } else if (t8 < 8 && t + 1 < SQ) {
            xnv = *(const float4*)(xin + ((size_t)xgb * SQ + t + 1) * 4);
        }

        // ---- GEMM: 4 gate rows x 2 batches, K-quarter kq ----
        unsigned long long acc[4][2];
#pragma unroll
        for (int g = 0; g < 4; g++) { acc[g][0] = 0ULL; acc[g][1] = 0ULL; }
#pragma unroll
        for (int m = 0; m < 4; m++) {
            ulonglong2 h0 = *(const ulonglong2*)(&hq[p][lb0][kq][4 * m]);
            ulonglong2 h1 = *(const ulonglong2*)(&hq[p][lb1][kq][4 * m]);
#pragma unroll
            for (int g = 0; g < 4; g++) {
                acc[g][0] = fma2(w[g][2 * m],     h0.x, acc[g][0]);
                acc[g][0] = fma2(w[g][2 * m + 1], h0.y, acc[g][0]);
                acc[g][1] = fma2(w[g][2 * m],     h1.x, acc[g][1]);
                acc[g][1] = fma2(w[g][2 * m + 1], h1.y, acc[g][1]);
            }
        }
        float S[4][2];
#pragma unroll
        for (int g = 0; g < 4; g++) {
            S[g][0] = lohi(acc[g][0]);
            S[g][1] = lohi(acc[g][1]);
        }
        if (MODE == 0 && kq == 0) {
            float4 xa  = xsm[p][lb0];
            float4 xbv = xsm[p][lb1];
#pragma unroll
            for (int g = 0; g < 4; g++) {
                S[g][0] += wi[g].x * xa.x + wi[g].y * xa.y + wi[g].z * xa.z + wi[g].w * xa.w;
                S[g][1] += wi[g].x * xbv.x + wi[g].y * xbv.y + wi[g].z * xbv.z + wi[g].w * xbv.w;
            }
        }

        // ---- merge (8 shfl): round A xor2 (batch swap) + round B xor1 ----
        float full[4];
#pragma unroll
        for (int g = 0; g < 4; g++) {
            float keep = fb ? S[g][1] : S[g][0];
            float send = fb ? S[g][0] : S[g][1];
            float T = keep + __shfl_xor_sync(0xffffffffu, send, 2);
            full[g] = T + __shfl_xor_sync(0xffffffffu, T, 1);
        }
#pragma unroll
        for (int g = 0; g < 4; g++)
            full[g] += (MODE == 0) ? bias[g] : xq[g];

        // ---- local LSTM update (tanh.approx) ----
        float iv = sigf(full[0]);
        float fv = sigf(full[1]);
        float gv = tanha(full[2]);
        float ov = sigf(full[3]);
        c = fv * c + iv * gv;
        float h = ov * tanha(c);

        if ((kq & 1) == 0) {
            hq[p ^ 1][lb][r6 >> 4][r6 & 15] = h;
            if (MODE != 2)
                dst[((size_t)t * BB + gb) * HID + r6] = h;
        }
        if (MODE == 0) {
            if (t8 < 8 && t + 1 < SQ) xsm[(t + 1) & 1][xlb] = xnv;
        } else {
#pragma unroll
            for (int g = 0; g < 4; g++) { xq[g] = xm[g]; xm[g] = xn[g]; }
        }
        asm volatile("bar.sync %0, 256;" :: "r"(grp + 1) : "memory");
    }

    if (MODE == 2) {
        __syncthreads();
        if (tid < 8) {
            int b = tid >> 1, o = tid & 1;
            float s = fcb[o];
#pragma unroll
            for (int j = 0; j < HID; j++)
                s += hq[0][b][j >> 4][j & 15] * fcw[o * HID + j];
            out[(blockIdx.x * 4 + b) * 2 + o] = s;
        }
    }
}

// ---------------------------------------------------------------------------
// Projection (R9 config — best measured): g_xp[row][col] = Wih[col,:].src+b
// grid=1024 x 512. kh = tid&1, r7 = (tid>>1)&127, dh = tid>>8.
// Thread: rows (r7, r7+128) x K-half kh (64 weight regs), 4 of 8 data rows.
// One xor-1 shfl merge; coalesced 64B-segment writes. Double-buffered smem.
// ---------------------------------------------------------------------------
#define PCTAS 1024
#define PROWS ((SQ * BB) / PCTAS)     // 1024
#define PITER (PROWS / 8)             // 128

template <int SRCB>
__global__ void __launch_bounds__(512, 1)
lstm_proj(const float* __restrict__ Wih,
          const float* __restrict__ bih, const float* __restrict__ bhh)
{
    const float* src = (SRCB == 0) ? g_bufA : g_bufB;
    __shared__ __align__(16) float xr[2][8][2][36];   // [buf][row][half][32+pad]

    const int tid = threadIdx.x;
    const int kh  = tid & 1;
    const int r7  = (tid >> 1) & 127;
    const int dh  = tid >> 8;
    const int col = r7 + 128 * kh;

    unsigned long long w0[16], w1[16];
#pragma unroll
    for (int m2 = 0; m2 < 16; m2++) {
        w0[m2] = *(const unsigned long long*)(Wih + (size_t)r7 * HID + 32 * kh + 2 * m2);
        w1[m2] = *(const unsigned long long*)(Wih + (size_t)(r7 + 128) * HID + 32 * kh + 2 * m2);
    }
    const float bias = bih[col] + bhh[col];

    const size_t row0 = (size_t)blockIdx.x * PROWS;

    float2 ld = make_float2(0.f, 0.f);
    if (tid < 256) {
        ld = *(const float2*)(src + (row0 + (tid >> 5)) * HID + 2 * (tid & 31));
        *(float2*)(&xr[0][tid >> 5][(tid & 31) >> 4][(2 * (tid & 31)) & 31]) = ld;
    }
    __syncthreads();

    for (int it = 0; it < PITER; it++) {
        const int p = it & 1;
        const size_t rb = row0 + (size_t)it * 8;

        if (it + 1 < PITER && tid < 256)
            ld = *(const float2*)(src + (rb + 8 + (tid >> 5)) * HID + 2 * (tid & 31));

        unsigned long long a0[4], a1[4];
#pragma unroll
        for (int dr = 0; dr < 4; dr++) { a0[dr] = 0ULL; a1[dr] = 0ULL; }
#pragma unroll
        for (int m = 0; m < 8; m++) {
#pragma unroll
            for (int dr = 0; dr < 4; dr++) {
                ulonglong2 hv = *(const ulonglong2*)(&xr[p][4 * dh + dr][kh][4 * m]);
                a0[dr] = fma2(w0[2 * m],     hv.x, a0[dr]);
                a0[dr] = fma2(w0[2 * m + 1], hv.y, a0[dr]);
                a1[dr] = fma2(w1[2 * m],     hv.x, a1[dr]);
                a1[dr] = fma2(w1[2 * m + 1], hv.y, a1[dr]);
            }
        }
#pragma unroll
        for (int dr = 0; dr < 4; dr++) {
            float s0 = lohi(a0[dr]);
            float s1 = lohi(a1[dr]);
            float send = kh ? s0 : s1;       // pass the row I don't finalize
            float recv = __shfl_xor_sync(0xffffffffu, send, 1);
            float full = (kh ? s1 : s0) + recv + bias;
            g_xp[(rb + 4 * dh + dr) * 256 + col] = full;
        }

        if (it + 1 < PITER && tid < 256)
            *(float2*)(&xr[p ^ 1][tid >> 5][(tid & 31) >> 4][(2 * (tid & 31)) & 31]) = ld;
        __syncthreads();
    }
}

extern "C" void kernel_launch(void* const* d_in, const int* in_sizes, int n_in,
                              void* d_out, int out_size)
{
    (void)in_sizes; (void)n_in; (void)out_size;
    const float* x    = (const float*)d_in[0];
    const float* Wih0 = (const float*)d_in[1];
    const float* Whh0 = (const float*)d_in[2];
    const float* bih0 = (const float*)d_in[3];
    const float* bhh0 = (const float*)d_in[4];
    const float* Wih1 = (const float*)d_in[5];
    const float* Whh1 = (const float*)d_in[6];
    const float* bih1 = (const float*)d_in[7];
    const float* bhh1 = (const float*)d_in[8];
    const float* Wih2 = (const float*)d_in[9];
    const float* Whh2 = (const float*)d_in[10];
    const float* bih2 = (const float*)d_in[11];
    const float* bhh2 = (const float*)d_in[12];
    const float* fc_w = (const float*)d_in[13];
    const float* fc_b = (const float*)d_in[14];
    float* out = (float*)d_out;

    dim3 rgrid(BB / 4), rblock(512);
    dim3 pgrid(PCTAS), pblock(512);

    lstm_rec<0><<<rgrid, rblock>>>(x, Wih0, Whh0, bih0, bhh0, nullptr, nullptr, nullptr);
    lstm_proj<0><<<pgrid, pblock>>>(Wih1, bih1, bhh1);
    lstm_rec<1><<<rgrid, rblock>>>(nullptr, nullptr, Whh1, nullptr, nullptr, nullptr, nullptr, nullptr);
    lstm_proj<1><<<pgrid, pblock>>>(Wih2, bih2, bhh2);
    lstm_rec<2><<<rgrid, rblock>>>(nullptr, nullptr, Whh2, nullptr, nullptr, fc_w, fc_b, out);
}

// round 14
// speedup vs baseline: 1.3389x; 1.3389x over previous
#include <cuda_runtime.h>
#include <cstdint>
#include <cstddef>

// 3-layer LSTM (H=64), S=2048, B=512, FC(64->2).
// rec: EXACT R10 version (measured best) — do not touch.
// proj R14: K-quarter split, 32 weight regs -> 2 CTAs x 512 (32 warps/SM),
//           6-shfl butterfly merge, rec-proven [4][20] quarter smem layout.

#define SQ   2048
#define BB   512
#define HID  64

static __device__ float g_bufA[(size_t)SQ * BB * HID];
static __device__ float g_bufB[(size_t)SQ * BB * HID];
static __device__ float g_xp  [(size_t)SQ * BB * 256];

__device__ __forceinline__ unsigned long long fma2(unsigned long long a,
                                                   unsigned long long b,
                                                   unsigned long long c) {
    unsigned long long d;
    asm("fma.rn.f32x2 %0, %1, %2, %3;" : "=l"(d) : "l"(a), "l"(b), "l"(c));
    return d;
}
__device__ __forceinline__ float lohi(unsigned long long u) {
    union { unsigned long long v; float2 f; } c; c.v = u;
    return c.f.x + c.f.y;
}
__device__ __forceinline__ float tanha(float x) {
    float y; asm("tanh.approx.f32 %0, %1;" : "=f"(y) : "f"(x)); return y;
}
__device__ __forceinline__ float sigf(float x) {
    return fmaf(0.5f, tanha(0.5f * x), 0.5f);
}

// ---------------------------------------------------------------------------
// Recurrence (EXACT R10). grid=128 CTAs x 512 threads; grp = tid>>8 owns
// 2 batches. t8 = tid&255: kq = t8&3, r6 = t8>>2. Thread holds Whh rows
// {r6, 64+r6, 128+r6, 192+r6}, K-quarter kq (64 regs). 12-shfl butterfly
// merge; lane finalizes batch fb = kq>>1 locally. hq double-buffered,
// ONE bar.sync(grp+1,256) per step.
// ---------------------------------------------------------------------------
template <int MODE>
__global__ void __launch_bounds__(512, 1)
lstm_rec(const float* __restrict__ xin,
         const float* __restrict__ Wih, const float* __restrict__ Whh,
         const float* __restrict__ bih, const float* __restrict__ bhh,
         const float* __restrict__ fcw, const float* __restrict__ fcb,
         float* __restrict__ out)
{
    __shared__ __align__(16) float hq[2][4][4][20];
    __shared__ __align__(16) float4 xsm[2][4];        // MODE 0 only

    const int tid = threadIdx.x;
    const int grp = tid >> 8;
    const int t8  = tid & 255;
    const int kq  = t8 & 3;
    const int r6  = t8 >> 2;
    const int fb  = kq >> 1;
    const int lb  = 2 * grp + fb;
    const int gb  = blockIdx.x * 4 + lb;
    const int lb0 = 2 * grp, lb1 = 2 * grp + 1;
    const int xlb = 2 * grp + ((t8 >> 2) & 1);
    const int xgb = blockIdx.x * 4 + xlb;

    unsigned long long w[4][8];
#pragma unroll
    for (int g = 0; g < 4; g++)
#pragma unroll
        for (int m2 = 0; m2 < 8; m2++)
            w[g][m2] = *(const unsigned long long*)
                (Whh + (size_t)(64 * g + r6) * HID + 16 * kq + 2 * m2);

    float4 wi[4]; float bias[4];
    if (MODE == 0) {
#pragma unroll
        for (int g = 0; g < 4; g++) {
            wi[g]   = *(const float4*)(Wih + (size_t)(64 * g + r6) * 4);
            bias[g] = bih[64 * g + r6] + bhh[64 * g + r6];
        }
    }

    float c = 0.f;
    if ((kq & 1) == 0) hq[0][lb][r6 >> 4][r6 & 15] = 0.f;

    const size_t xstr = (size_t)BB * 256;
    const float* xb = g_xp + (size_t)gb * 256 + r6;
    float xq[4], xm[4];
    if (MODE != 0) {
#pragma unroll
        for (int g = 0; g < 4; g++) {
            xq[g] = xb[64 * g];
            xm[g] = xb[xstr + 64 * g];
        }
    } else if (t8 < 8) {
        xsm[0][xlb] = *(const float4*)(xin + (size_t)xgb * SQ * 4);
    }
    __syncthreads();

    float* dst = (MODE == 0) ? g_bufA : g_bufB;

    for (int t = 0; t < SQ; t++) {
        const int p = t & 1;

        float xn[4]; float4 xnv;
        if (MODE != 0) {
            if (t + 2 < SQ) {
                const float* q = xb + (size_t)(t + 2) * xstr;
#pragma unroll
                for (int g = 0; g < 4; g++) xn[g] = q[64 * g];
            } else {
#pragma unroll
                for (int g = 0; g < 4; g++) xn[g] = 0.f;
            }
        } else if (t8 < 8 && t + 1 < SQ) {
            xnv = *(const float4*)(xin + ((size_t)xgb * SQ + t + 1) * 4);
        }

        unsigned long long acc[4][2];
#pragma unroll
        for (int g = 0; g < 4; g++) { acc[g][0] = 0ULL; acc[g][1] = 0ULL; }
#pragma unroll
        for (int m = 0; m < 4; m++) {
            ulonglong2 h0 = *(const ulonglong2*)(&hq[p][lb0][kq][4 * m]);
            ulonglong2 h1 = *(const ulonglong2*)(&hq[p][lb1][kq][4 * m]);
#pragma unroll
            for (int g = 0; g < 4; g++) {
                acc[g][0] = fma2(w[g][2 * m],     h0.x, acc[g][0]);
                acc[g][0] = fma2(w[g][2 * m + 1], h0.y, acc[g][0]);
                acc[g][1] = fma2(w[g][2 * m],     h1.x, acc[g][1]);
                acc[g][1] = fma2(w[g][2 * m + 1], h1.y, acc[g][1]);
            }
        }
        float S[4][2];
#pragma unroll
        for (int g = 0; g < 4; g++) {
            S[g][0] = lohi(acc[g][0]);
            S[g][1] = lohi(acc[g][1]);
        }
        if (MODE == 0 && kq == 0) {
            float4 xa  = xsm[p][lb0];
            float4 xbv = xsm[p][lb1];
#pragma unroll
            for (int g = 0; g < 4; g++) {
                S[g][0] += wi[g].x * xa.x + wi[g].y * xa.y + wi[g].z * xa.z + wi[g].w * xa.w;
                S[g][1] += wi[g].x * xbv.x + wi[g].y * xbv.y + wi[g].z * xbv.z + wi[g].w * xbv.w;
            }
        }

        // ---- merge over kq (R10 12-shfl version) ----
        float full[4];
#pragma unroll
        for (int g = 0; g < 4; g++) {
            S[g][0] += __shfl_xor_sync(0xffffffffu, S[g][0], 1);
            S[g][1] += __shfl_xor_sync(0xffffffffu, S[g][1], 1);
        }
#pragma unroll
        for (int g = 0; g < 4; g++) {
            float own  = fb ? S[g][1] : S[g][0];
            float send = fb ? S[g][0] : S[g][1];
            float recv = __shfl_xor_sync(0xffffffffu, send, 2);
            full[g] = own + recv;
        }
#pragma unroll
        for (int g = 0; g < 4; g++)
            full[g] += (MODE == 0) ? bias[g] : xq[g];

        float iv = sigf(full[0]);
        float fv = sigf(full[1]);
        float gv = tanha(full[2]);
        float ov = sigf(full[3]);
        c = fv * c + iv * gv;
        float h = ov * tanha(c);

        if ((kq & 1) == 0) {
            hq[p ^ 1][lb][r6 >> 4][r6 & 15] = h;
            if (MODE != 2)
                dst[((size_t)t * BB + gb) * HID + r6] = h;
        }
        if (MODE == 0) {
            if (t8 < 8 && t + 1 < SQ) xsm[(t + 1) & 1][xlb] = xnv;
        } else {
#pragma unroll
            for (int g = 0; g < 4; g++) { xq[g] = xm[g]; xm[g] = xn[g]; }
        }
        asm volatile("bar.sync %0, 256;" :: "r"(grp + 1) : "memory");
    }

    if (MODE == 2) {
        __syncthreads();
        if (tid < 8) {
            int b = tid >> 1, o = tid & 1;
            float s = fcb[o];
#pragma unroll
            for (int j = 0; j < HID; j++)
                s += hq[0][b][j >> 4][j & 15] * fcw[o * HID + j];
            out[(blockIdx.x * 4 + b) * 2 + o] = s;
        }
    }
}

// ---------------------------------------------------------------------------
// Projection R14: g_xp[row][col] = Wih[col,:] . src[row,:] + bias[col]
// grid=2048 x 512 threads, 2 CTAs/SM. kq = tid&3 (K-quarter, lane bits 0-1),
// r7 = tid>>2. Thread: rows (r7, r7+128) x K-quarter kq (32 weight regs),
// 4 data rows/iter (16 acc regs). Merge: xor2 (data-row-half swap) then
// xor1 (col-half swap); lane finalizes col ch=kq&1, rows 2*(kq>>1)+{0,1}.
// Quarter smem layout [4][20] (16B-aligned, banks disjoint). Double-buffered.
// ---------------------------------------------------------------------------
#define PCTAS 2048
#define PROWS ((SQ * BB) / PCTAS)     // 512
#define PITER (PROWS / 4)             // 128

template <int SRCB>
__global__ void __launch_bounds__(512, 2)
lstm_proj(const float* __restrict__ Wih,
          const float* __restrict__ bih, const float* __restrict__ bhh)
{
    const float* src = (SRCB == 0) ? g_bufA : g_bufB;
    __shared__ __align__(16) float xr[2][4][4][20];   // [buf][row][quarter][16+4]

    const int tid = threadIdx.x;
    const int kq  = tid & 3;
    const int r7  = tid >> 2;            // 0..127
    const int ch  = kq & 1;              // col half this lane finalizes
    const int dhh = kq >> 1;             // data-row half this lane finalizes
    const int col = r7 + 128 * ch;

    unsigned long long w0[8], w1[8];
#pragma unroll
    for (int m2 = 0; m2 < 8; m2++) {
        w0[m2] = *(const unsigned long long*)(Wih + (size_t)r7 * HID + 16 * kq + 2 * m2);
        w1[m2] = *(const unsigned long long*)(Wih + (size_t)(r7 + 128) * HID + 16 * kq + 2 * m2);
    }
    const float bias = bih[col] + bhh[col];

    const size_t row0 = (size_t)blockIdx.x * PROWS;

    // staging: threads 0..127 carry one float2 (4 rows x 64 floats)
    float2 ld = make_float2(0.f, 0.f);
    if (tid < 128) {
        int srow = tid >> 5, c2 = tid & 31, colx = 2 * c2;
        ld = *(const float2*)(src + (row0 + srow) * HID + colx);
        *(float2*)(&xr[0][srow][colx >> 4][colx & 15]) = ld;
    }
    __syncthreads();

    for (int it = 0; it < PITER; it++) {
        const int p = it & 1;
        const size_t rb = row0 + (size_t)it * 4;

        if (it + 1 < PITER && tid < 128) {
            int srow = tid >> 5, c2 = tid & 31, colx = 2 * c2;
            ld = *(const float2*)(src + (rb + 4 + srow) * HID + colx);
        }

        // ---- GEMM: 2 cols x 4 data rows, K-quarter kq ----
        unsigned long long a0[4], a1[4];
#pragma unroll
        for (int dr = 0; dr < 4; dr++) { a0[dr] = 0ULL; a1[dr] = 0ULL; }
#pragma unroll
        for (int m = 0; m < 4; m++) {
#pragma unroll
            for (int dr = 0; dr < 4; dr++) {
                ulonglong2 hv = *(const ulonglong2*)(&xr[p][dr][kq][4 * m]);
                a0[dr] = fma2(w0[2 * m],     hv.x, a0[dr]);
                a0[dr] = fma2(w0[2 * m + 1], hv.y, a0[dr]);
                a1[dr] = fma2(w1[2 * m],     hv.x, a1[dr]);
                a1[dr] = fma2(w1[2 * m + 1], hv.y, a1[dr]);
            }
        }
        float S0[4], S1[4];
#pragma unroll
        for (int dr = 0; dr < 4; dr++) {
            S0[dr] = lohi(a0[dr]);
            S1[dr] = lohi(a1[dr]);
        }

        // ---- round A (xor 2): keep my data-row half, swap the other ----
        float k00 = dhh ? S0[2] : S0[0];   // col0, my row a
        float k01 = dhh ? S0[3] : S0[1];   // col0, my row b
        float s00 = dhh ? S0[0] : S0[2];
        float s01 = dhh ? S0[1] : S0[3];
        float k10 = dhh ? S1[2] : S1[0];   // col1, my row a
        float k11 = dhh ? S1[3] : S1[1];
        float s10 = dhh ? S1[0] : S1[2];
        float s11 = dhh ? S1[1] : S1[3];
        float T00 = k00 + __shfl_xor_sync(0xffffffffu, s00, 2);
        float T01 = k01 + __shfl_xor_sync(0xffffffffu, s01, 2);
        float T10 = k10 + __shfl_xor_sync(0xffffffffu, s10, 2);
        float T11 = k11 + __shfl_xor_sync(0xffffffffu, s11, 2);

        // ---- round B (xor 1): keep my col half, swap the other ----
        float ka = ch ? T10 : T00, sa = ch ? T00 : T10;
        float kb = ch ? T11 : T01, sb = ch ? T01 : T11;
        float fa = ka + __shfl_xor_sync(0xffffffffu, sa, 1) + bias;
        float fbv = kb + __shfl_xor_sync(0xffffffffu, sb, 1) + bias;

        g_xp[(rb + 2 * dhh + 0) * 256 + col] = fa;
        g_xp[(rb + 2 * dhh + 1) * 256 + col] = fbv;

        if (it + 1 < PITER && tid < 128) {
            int srow = tid >> 5, c2 = tid & 31, colx = 2 * c2;
            *(float2*)(&xr[p ^ 1][srow][colx >> 4][colx & 15]) = ld;
        }
        __syncthreads();
    }
}

extern "C" void kernel_launch(void* const* d_in, const int* in_sizes, int n_in,
                              void* d_out, int out_size)
{
    (void)in_sizes; (void)n_in; (void)out_size;
    const float* x    = (const float*)d_in[0];
    const float* Wih0 = (const float*)d_in[1];
    const float* Whh0 = (const float*)d_in[2];
    const float* bih0 = (const float*)d_in[3];
    const float* bhh0 = (const float*)d_in[4];
    const float* Wih1 = (const float*)d_in[5];
    const float* Whh1 = (const float*)d_in[6];
    const float* bih1 = (const float*)d_in[7];
    const float* bhh1 = (const float*)d_in[8];
    const float* Wih2 = (const float*)d_in[9];
    const float* Whh2 = (const float*)d_in[10];
    const float* bih2 = (const float*)d_in[11];
    const float* bhh2 = (const float*)d_in[12];
    const float* fc_w = (const float*)d_in[13];
    const float* fc_b = (const float*)d_in[14];
    float* out = (float*)d_out;

    dim3 rgrid(BB / 4), rblock(512);
    dim3 pgrid(PCTAS), pblock(512);

    lstm_rec<0><<<rgrid, rblock>>>(x, Wih0, Whh0, bih0, bhh0, nullptr, nullptr, nullptr);
    lstm_proj<0><<<pgrid, pblock>>>(Wih1, bih1, bhh1);
    lstm_rec<1><<<rgrid, rblock>>>(nullptr, nullptr, Whh1, nullptr, nullptr, nullptr, nullptr, nullptr);
    lstm_proj<1><<<pgrid, pblock>>>(Wih2, bih2, bhh2);
    lstm_rec<2><<<rgrid, rblock>>>(nullptr, nullptr, Whh2, nullptr, nullptr, fc_w, fc_b, out);
}

// round 15
// speedup vs baseline: 1.5710x; 1.1733x over previous
#include <cuda_runtime.h>
#include <cstdint>
#include <cstddef>

// 3-layer LSTM (H=64), S=2048, B=512, FC(64->2).
// R15 = compose of measured-best components, no new experiments:
//   rec  = R10 text exactly (validated via R14 accounting): thread owns 4
//          gate rows of one column (K-quarter each, 64 weight regs),
//          12-shfl butterfly merge, local c/h update, tanh.approx,
//          ONE named barrier per step, double-buffered h.
//   proj = R9 text exactly (best measured 860us): grid 1024 x 512,
//          rows (r7, r7+128) x K-half, 8 rows/iter, one xor-1 merge.

#define SQ   2048
#define BB   512
#define HID  64

static __device__ float g_bufA[(size_t)SQ * BB * HID];
static __device__ float g_bufB[(size_t)SQ * BB * HID];
static __device__ float g_xp  [(size_t)SQ * BB * 256];

__device__ __forceinline__ unsigned long long fma2(unsigned long long a,
                                                   unsigned long long b,
                                                   unsigned long long c) {
    unsigned long long d;
    asm("fma.rn.f32x2 %0, %1, %2, %3;" : "=l"(d) : "l"(a), "l"(b), "l"(c));
    return d;
}
__device__ __forceinline__ float lohi(unsigned long long u) {
    union { unsigned long long v; float2 f; } c; c.v = u;
    return c.f.x + c.f.y;
}
__device__ __forceinline__ float tanha(float x) {
    float y; asm("tanh.approx.f32 %0, %1;" : "=f"(y) : "f"(x)); return y;
}
__device__ __forceinline__ float sigf(float x) {
    return fmaf(0.5f, tanha(0.5f * x), 0.5f);
}

// ---------------------------------------------------------------------------
// Recurrence (R10 exact). grid=128 CTAs x 512 threads; grp = tid>>8 owns
// 2 batches. t8 = tid&255: kq = t8&3, r6 = t8>>2. Thread holds Whh rows
// {r6, 64+r6, 128+r6, 192+r6}, K-quarter kq (64 regs). 12-shfl butterfly
// merge; lane finalizes batch fb = kq>>1 locally. hq double-buffered,
// ONE bar.sync(grp+1,256) per step.
// MODE: 0 = layer0 (x inline, h->bufA), 1 = mid (xp in, h->bufB),
//       2 = final (xp in, FC->out).
// ---------------------------------------------------------------------------
template <int MODE>
__global__ void __launch_bounds__(512, 1)
lstm_rec(const float* __restrict__ xin,
         const float* __restrict__ Wih, const float* __restrict__ Whh,
         const float* __restrict__ bih, const float* __restrict__ bhh,
         const float* __restrict__ fcw, const float* __restrict__ fcb,
         float* __restrict__ out)
{
    __shared__ __align__(16) float hq[2][4][4][20];
    __shared__ __align__(16) float4 xsm[2][4];        // MODE 0 only

    const int tid = threadIdx.x;
    const int grp = tid >> 8;
    const int t8  = tid & 255;
    const int kq  = t8 & 3;
    const int r6  = t8 >> 2;
    const int fb  = kq >> 1;
    const int lb  = 2 * grp + fb;
    const int gb  = blockIdx.x * 4 + lb;
    const int lb0 = 2 * grp, lb1 = 2 * grp + 1;
    const int xlb = 2 * grp + ((t8 >> 2) & 1);
    const int xgb = blockIdx.x * 4 + xlb;

    unsigned long long w[4][8];
#pragma unroll
    for (int g = 0; g < 4; g++)
#pragma unroll
        for (int m2 = 0; m2 < 8; m2++)
            w[g][m2] = *(const unsigned long long*)
                (Whh + (size_t)(64 * g + r6) * HID + 16 * kq + 2 * m2);

    float4 wi[4]; float bias[4];
    if (MODE == 0) {
#pragma unroll
        for (int g = 0; g < 4; g++) {
            wi[g]   = *(const float4*)(Wih + (size_t)(64 * g + r6) * 4);
            bias[g] = bih[64 * g + r6] + bhh[64 * g + r6];
        }
    }

    float c = 0.f;
    if ((kq & 1) == 0) hq[0][lb][r6 >> 4][r6 & 15] = 0.f;

    const size_t xstr = (size_t)BB * 256;
    const float* xb = g_xp + (size_t)gb * 256 + r6;
    float xq[4], xm[4];
    if (MODE != 0) {
#pragma unroll
        for (int g = 0; g < 4; g++) {
            xq[g] = xb[64 * g];
            xm[g] = xb[xstr + 64 * g];
        }
    } else if (t8 < 8) {
        xsm[0][xlb] = *(const float4*)(xin + (size_t)xgb * SQ * 4);
    }
    __syncthreads();

    float* dst = (MODE == 0) ? g_bufA : g_bufB;

    for (int t = 0; t < SQ; t++) {
        const int p = t & 1;

        float xn[4]; float4 xnv;
        if (MODE != 0) {
            if (t + 2 < SQ) {
                const float* q = xb + (size_t)(t + 2) * xstr;
#pragma unroll
                for (int g = 0; g < 4; g++) xn[g] = q[64 * g];
            } else {
#pragma unroll
                for (int g = 0; g < 4; g++) xn[g] = 0.f;
            }
        } else if (t8 < 8 && t + 1 < SQ) {
            xnv = *(const float4*)(xin + ((size_t)xgb * SQ + t + 1) * 4);
        }

        unsigned long long acc[4][2];
#pragma unroll
        for (int g = 0; g < 4; g++) { acc[g][0] = 0ULL; acc[g][1] = 0ULL; }
#pragma unroll
        for (int m = 0; m < 4; m++) {
            ulonglong2 h0 = *(const ulonglong2*)(&hq[p][lb0][kq][4 * m]);
            ulonglong2 h1 = *(const ulonglong2*)(&hq[p][lb1][kq][4 * m]);
#pragma unroll
            for (int g = 0; g < 4; g++) {
                acc[g][0] = fma2(w[g][2 * m],     h0.x, acc[g][0]);
                acc[g][0] = fma2(w[g][2 * m + 1], h0.y, acc[g][0]);
                acc[g][1] = fma2(w[g][2 * m],     h1.x, acc[g][1]);
                acc[g][1] = fma2(w[g][2 * m + 1], h1.y, acc[g][1]);
            }
        }
        float S[4][2];
#pragma unroll
        for (int g = 0; g < 4; g++) {
            S[g][0] = lohi(acc[g][0]);
            S[g][1] = lohi(acc[g][1]);
        }
        if (MODE == 0 && kq == 0) {
            float4 xa  = xsm[p][lb0];
            float4 xbv = xsm[p][lb1];
#pragma unroll
            for (int g = 0; g < 4; g++) {
                S[g][0] += wi[g].x * xa.x + wi[g].y * xa.y + wi[g].z * xa.z + wi[g].w * xa.w;
                S[g][1] += wi[g].x * xbv.x + wi[g].y * xbv.y + wi[g].z * xbv.z + wi[g].w * xbv.w;
            }
        }

        // ---- merge over kq (12-shfl) ----
        float full[4];
#pragma unroll
        for (int g = 0; g < 4; g++) {
            S[g][0] += __shfl_xor_sync(0xffffffffu, S[g][0], 1);
            S[g][1] += __shfl_xor_sync(0xffffffffu, S[g][1], 1);
        }
#pragma unroll
        for (int g = 0; g < 4; g++) {
            float own  = fb ? S[g][1] : S[g][0];
            float send = fb ? S[g][0] : S[g][1];
            float recv = __shfl_xor_sync(0xffffffffu, send, 2);
            full[g] = own + recv;
        }
#pragma unroll
        for (int g = 0; g < 4; g++)
            full[g] += (MODE == 0) ? bias[g] : xq[g];

        float iv = sigf(full[0]);
        float fv = sigf(full[1]);
        float gv = tanha(full[2]);
        float ov = sigf(full[3]);
        c = fv * c + iv * gv;
        float h = ov * tanha(c);

        if ((kq & 1) == 0) {
            hq[p ^ 1][lb][r6 >> 4][r6 & 15] = h;
            if (MODE != 2)
                dst[((size_t)t * BB + gb) * HID + r6] = h;
        }
        if (MODE == 0) {
            if (t8 < 8 && t + 1 < SQ) xsm[(t + 1) & 1][xlb] = xnv;
        } else {
#pragma unroll
            for (int g = 0; g < 4; g++) { xq[g] = xm[g]; xm[g] = xn[g]; }
        }
        asm volatile("bar.sync %0, 256;" :: "r"(grp + 1) : "memory");
    }

    if (MODE == 2) {
        __syncthreads();
        if (tid < 8) {
            int b = tid >> 1, o = tid & 1;
            float s = fcb[o];
#pragma unroll
            for (int j = 0; j < HID; j++)
                s += hq[0][b][j >> 4][j & 15] * fcw[o * HID + j];
            out[(blockIdx.x * 4 + b) * 2 + o] = s;
        }
    }
}

// ---------------------------------------------------------------------------
// Projection (R9 exact — best measured): g_xp[row][col] = Wih[col,:].src+b
// grid=1024 x 512. kh = tid&1, r7 = (tid>>1)&127, dh = tid>>8.
// Thread: rows (r7, r7+128) x K-half kh (64 weight regs), 4 of 8 data rows.
// One xor-1 shfl merge; coalesced 64B-segment writes. Double-buffered smem.
// ---------------------------------------------------------------------------
#define PCTAS 1024
#define PROWS ((SQ * BB) / PCTAS)     // 1024
#define PITER (PROWS / 8)             // 128

template <int SRCB>
__global__ void __launch_bounds__(512, 1)
lstm_proj(const float* __restrict__ Wih,
          const float* __restrict__ bih, const float* __restrict__ bhh)
{
    const float* src = (SRCB == 0) ? g_bufA : g_bufB;
    __shared__ __align__(16) float xr[2][8][2][36];   // [buf][row][half][32+pad]

    const int tid = threadIdx.x;
    const int kh  = tid & 1;
    const int r7  = (tid >> 1) & 127;
    const int dh  = tid >> 8;
    const int col = r7 + 128 * kh;

    unsigned long long w0[16], w1[16];
#pragma unroll
    for (int m2 = 0; m2 < 16; m2++) {
        w0[m2] = *(const unsigned long long*)(Wih + (size_t)r7 * HID + 32 * kh + 2 * m2);
        w1[m2] = *(const unsigned long long*)(Wih + (size_t)(r7 + 128) * HID + 32 * kh + 2 * m2);
    }
    const float bias = bih[col] + bhh[col];

    const size_t row0 = (size_t)blockIdx.x * PROWS;

    float2 ld = make_float2(0.f, 0.f);
    if (tid < 256) {
        ld = *(const float2*)(src + (row0 + (tid >> 5)) * HID + 2 * (tid & 31));
        *(float2*)(&xr[0][tid >> 5][(tid & 31) >> 4][(2 * (tid & 31)) & 31]) = ld;
    }
    __syncthreads();

    for (int it = 0; it < PITER; it++) {
        const int p = it & 1;
        const size_t rb = row0 + (size_t)it * 8;

        if (it + 1 < PITER && tid < 256)
            ld = *(const float2*)(src + (rb + 8 + (tid >> 5)) * HID + 2 * (tid & 31));

        unsigned long long a0[4], a1[4];
#pragma unroll
        for (int dr = 0; dr < 4; dr++) { a0[dr] = 0ULL; a1[dr] = 0ULL; }
#pragma unroll
        for (int m = 0; m < 8; m++) {
#pragma unroll
            for (int dr = 0; dr < 4; dr++) {
                ulonglong2 hv = *(const ulonglong2*)(&xr[p][4 * dh + dr][kh][4 * m]);
                a0[dr] = fma2(w0[2 * m],     hv.x, a0[dr]);
                a0[dr] = fma2(w0[2 * m + 1], hv.y, a0[dr]);
                a1[dr] = fma2(w1[2 * m],     hv.x, a1[dr]);
                a1[dr] = fma2(w1[2 * m + 1], hv.y, a1[dr]);
            }
        }
#pragma unroll
        for (int dr = 0; dr < 4; dr++) {
            float s0 = lohi(a0[dr]);
            float s1 = lohi(a1[dr]);
            float send = kh ? s0 : s1;       // pass the row I don't finalize
            float recv = __shfl_xor_sync(0xffffffffu, send, 1);
            float full = (kh ? s1 : s0) + recv + bias;
            g_xp[(rb + 4 * dh + dr) * 256 + col] = full;
        }

        if (it + 1 < PITER && tid < 256)
            *(float2*)(&xr[p ^ 1][tid >> 5][(tid & 31) >> 4][(2 * (tid & 31)) & 31]) = ld;
        __syncthreads();
    }
}

extern "C" void kernel_launch(void* const* d_in, const int* in_sizes, int n_in,
                              void* d_out, int out_size)
{
    (void)in_sizes; (void)n_in; (void)out_size;
    const float* x    = (const float*)d_in[0];
    const float* Wih0 = (const float*)d_in[1];
    const float* Whh0 = (const float*)d_in[2];
    const float* bih0 = (const float*)d_in[3];
    const float* bhh0 = (const float*)d_in[4];
    const float* Wih1 = (const float*)d_in[5];
    const float* Whh1 = (const float*)d_in[6];
    const float* bih1 = (const float*)d_in[7];
    const float* bhh1 = (const float*)d_in[8];
    const float* Wih2 = (const float*)d_in[9];
    const float* Whh2 = (const float*)d_in[10];
    const float* bih2 = (const float*)d_in[11];
    const float* bhh2 = (const float*)d_in[12];
    const float* fc_w = (const float*)d_in[13];
    const float* fc_b = (const float*)d_in[14];
    float* out = (float*)d_out;

    dim3 rgrid(BB / 4), rblock(512);
    dim3 pgrid(PCTAS), pblock(512);

    lstm_rec<0><<<rgrid, rblock>>>(x, Wih0, Whh0, bih0, bhh0, nullptr, nullptr, nullptr);
    lstm_proj<0><<<pgrid, pblock>>>(Wih1, bih1, bhh1);
    lstm_rec<1><<<rgrid, rblock>>>(nullptr, nullptr, Whh1, nullptr, nullptr, nullptr, nullptr, nullptr);
    lstm_proj<1><<<pgrid, pblock>>>(Wih2, bih2, bhh2);
    lstm_rec<2><<<rgrid, rblock>>>(nullptr, nullptr, Whh2, nullptr, nullptr, fc_w, fc_b, out);
}